// round 5
// baseline (speedup 1.0000x reference)
#include <cuda_runtime.h>
#include <cstdint>

// Problem constants: B=8, N=500000, H=W=512, HALF_CENTOR=true
#define BB    8
#define NPTS  500000
#define HH    512
#define WW    512
#define NCELL (BB * HH * WW)   // 2,097,152 cells

// One 64-bit word per cell: high 32 = m = ~enc_f(min cost) (0 == empty, any
// finite cost encodes to m >= 1), low 32 = count. Zero-initialized at module
// load; k_final restores zeros after reading, so every call sees zeros.
__device__ unsigned long long g_cell64[NCELL];   // 16 MB, L2-resident

// Order-preserving float -> uint (monotone increasing).
__device__ __forceinline__ unsigned int enc_f(float f) {
    unsigned int u = __float_as_uint(f);
    return (u & 0x80000000u) ? ~u : (u | 0x80000000u);
}
__device__ __forceinline__ float dec_f(unsigned int u) {
    return __uint_as_float((u & 0x80000000u) ? (u & 0x7FFFFFFFu) : ~u);
}

// Single-atomic update of (min,count) via 64-bit CAS with an L2-load guess.
__device__ __forceinline__ void update_cell(int cell, float c) {
    unsigned int mkey = ~enc_f(c);               // bigger == smaller cost, >=1
    unsigned long long* addr = &g_cell64[cell];
    unsigned long long cur = __ldcg((const unsigned long long*)addr);
    #pragma unroll 1
    while (true) {
        unsigned int m = (unsigned int)(cur >> 32);
        if (mkey > m) m = mkey;
        unsigned long long nv =
            ((unsigned long long)m << 32) | (unsigned int)((unsigned int)cur + 1u);
        unsigned long long old = atomicCAS(addr, cur, nv);
        if (old == cur) break;                   // success (common case)
        cur = old;                               // rare retry under contention
    }
}

// ---------------------------------------------------------------------------
// Scatter: 2 points per thread. grid = (ceil(N/2/256), B).
// Streaming loads (__ldcs) keep L2 for the scratch array.
// ---------------------------------------------------------------------------
__global__ void k_scatter(const float4* __restrict__ points2,  // [B, N/2] (x0,y0,x1,y1)
                          const float2* __restrict__ costs2) { // [B, N/2]
    int t = blockIdx.x * blockDim.x + threadIdx.x;
    int b = blockIdx.y;
    if (t >= NPTS / 2) return;
    int gi = b * (NPTS / 2) + t;
    float4 p = __ldcs(&points2[gi]);
    float2 c = __ldcs(&costs2[gi]);

    int ix0 = (int)floorf(p.x + 0.5f);
    int iy0 = (int)floorf(p.y + 0.5f);
    int ix1 = (int)floorf(p.z + 0.5f);
    int iy1 = (int)floorf(p.w + 0.5f);

    if ((unsigned)ix0 < (unsigned)WW && (unsigned)iy0 < (unsigned)HH)
        update_cell((b * HH + iy0) * WW + ix0, c.x);
    if ((unsigned)ix1 < (unsigned)WW && (unsigned)iy1 < (unsigned)HH)
        update_cell((b * HH + iy1) * WW + ix1, c.y);
}

// ---------------------------------------------------------------------------
// Finalize: 8 cells per thread, 4x uint4 loads issued up-front (MLP=4).
// Output via streaming stores (__stwt) to avoid evicting the scratch from L2.
// Restores zero sentinels afterwards.
// ---------------------------------------------------------------------------
__global__ void k_final(float* __restrict__ out_cost,
                        float* __restrict__ out_mask,
                        const float* __restrict__ default_cost) {
    int i = blockIdx.x * blockDim.x + threadIdx.x;   // group of 8 cells
    if (i >= NCELL / 8) return;
    const uint4* cellv = reinterpret_cast<const uint4*>(g_cell64);
    // uint4 = one cell: (cnt, m) little-endian within the u64 -> x=cnt0, y=m0, z=cnt1, w=m1
    uint4 v0 = cellv[4 * i + 0];
    uint4 v1 = cellv[4 * i + 1];
    uint4 v2 = cellv[4 * i + 2];
    uint4 v3 = cellv[4 * i + 3];

    float d = __ldg(default_cost);

    float4 c0, c1, m0, m1;
    c0.x = v0.x ? dec_f(~v0.y) : d;  m0.x = (float)((int)v0.x - 1);
    c0.y = v0.z ? dec_f(~v0.w) : d;  m0.y = (float)((int)v0.z - 1);
    c0.z = v1.x ? dec_f(~v1.y) : d;  m0.z = (float)((int)v1.x - 1);
    c0.w = v1.z ? dec_f(~v1.w) : d;  m0.w = (float)((int)v1.z - 1);
    c1.x = v2.x ? dec_f(~v2.y) : d;  m1.x = (float)((int)v2.x - 1);
    c1.y = v2.z ? dec_f(~v2.w) : d;  m1.y = (float)((int)v2.z - 1);
    c1.z = v3.x ? dec_f(~v3.y) : d;  m1.z = (float)((int)v3.x - 1);
    c1.w = v3.z ? dec_f(~v3.w) : d;  m1.w = (float)((int)v3.z - 1);

    __stwt(&reinterpret_cast<float4*>(out_cost)[2 * i + 0], c0);
    __stwt(&reinterpret_cast<float4*>(out_cost)[2 * i + 1], c1);
    if (out_mask) {
        __stwt(&reinterpret_cast<float4*>(out_mask)[2 * i + 0], m0);
        __stwt(&reinterpret_cast<float4*>(out_mask)[2 * i + 1], m1);
    }

    // restore zero sentinels (stays in L2 for the next replay)
    uint4 z = make_uint4(0u, 0u, 0u, 0u);
    uint4* cellw = reinterpret_cast<uint4*>(g_cell64);
    cellw[4 * i + 0] = z;
    cellw[4 * i + 1] = z;
    cellw[4 * i + 2] = z;
    cellw[4 * i + 3] = z;
}

// ---------------------------------------------------------------------------
// Launcher. Inputs: points[B,N,2] f32, costs[B,N] f32, default_cost f32,
// height i32, width i32. Output: [cost | mask] as f32.
// ---------------------------------------------------------------------------
extern "C" void kernel_launch(void* const* d_in, const int* in_sizes, int n_in,
                              void* d_out, int out_size) {
    const float4* points2      = (const float4*)d_in[0];
    const float2* costs2       = (const float2*)d_in[1];
    const float*  default_cost = (const float*)d_in[2];

    float* out_cost = (float*)d_out;
    float* out_mask = (out_size >= 2 * NCELL) ? out_cost + NCELL : nullptr;

    const int T = 256;
    dim3 sg((NPTS / 2 + T - 1) / T, BB);
    k_scatter<<<sg, T>>>(points2, costs2);

    k_final<<<(NCELL / 8 + T - 1) / T, T>>>(out_cost, out_mask, default_cost);
}

// round 6
// speedup vs baseline: 1.3226x; 1.3226x over previous
#include <cuda_runtime.h>
#include <cstdint>

// Problem constants: B=8, N=500000, H=W=512, HALF_CENTOR=true
#define BB    8
#define NPTS  500000
#define HH    512
#define WW    512
#define NCELL (BB * HH * WW)   // 2,097,152 cells

// Separate scratch arrays (same-sector min+cnt atomics serialize in one LTS
// atomic bank; separate 8 MB arrays hash to different partitions).
// Sentinel is 0 for both (module-load zero init); k_final restores zeros after
// reading, so every kernel_launch call sees zeros on entry.
//   g_min[cell] = max over points of mkey = ~enc_f(cost); bigger == smaller
//                 cost, and every finite cost gives mkey >= 0x00800000 > 0.
//   g_cnt[cell] = number of points in the cell.
__device__ unsigned int g_min[NCELL];   // 8 MB
__device__ unsigned int g_cnt[NCELL];   // 8 MB

// Order-preserving float -> uint (monotone increasing).
__device__ __forceinline__ unsigned int enc_f(float f) {
    unsigned int u = __float_as_uint(f);
    return (u & 0x80000000u) ? ~u : (u | 0x80000000u);
}
__device__ __forceinline__ float dec_f(unsigned int u) {
    return __uint_as_float((u & 0x80000000u) ? (u & 0x7FFFFFFFu) : ~u);
}

// ---------------------------------------------------------------------------
// Scatter: 1 point per thread (round-1 proven shape). grid = (ceil(N/256), B).
// Guard-load before the min RED: skipping is safe whenever the current key is
// already >= mkey (max can't change). Moves ~1/3 of min traffic from the
// saturated LTS atomic-ALU path onto the wide LTS load path.
// ---------------------------------------------------------------------------
__global__ void k_scatter(const float2* __restrict__ points,  // [B*N] (x,y)
                          const float*  __restrict__ costs) { // [B*N]
    int n = blockIdx.x * blockDim.x + threadIdx.x;
    int b = blockIdx.y;
    if (n >= NPTS) return;
    int gi = b * NPTS + n;
    float2 p = __ldcs(&points[gi]);

    int ix = (int)floorf(p.x + 0.5f);
    int iy = (int)floorf(p.y + 0.5f);
    if ((unsigned)ix < (unsigned)WW && (unsigned)iy < (unsigned)HH) {
        int cell = (b * HH + iy) * WW + ix;
        float c = __ldcs(&costs[gi]);
        unsigned int mkey = ~enc_f(c);
        if (__ldcg(&g_min[cell]) < mkey)
            atomicMax(&g_min[cell], mkey);   // RED (result unused)
        atomicAdd(&g_cnt[cell], 1u);         // RED
    }
}

// ---------------------------------------------------------------------------
// Finalize: 4 cells per thread (round-2 proven shape), plain stores.
// Decodes min or default, emits mask = count-1, restores zero sentinels.
// ---------------------------------------------------------------------------
__global__ void k_final(float* __restrict__ out_cost,
                        float* __restrict__ out_mask,
                        const float* __restrict__ default_cost) {
    int i = blockIdx.x * blockDim.x + threadIdx.x;   // group of 4 cells
    if (i >= NCELL / 4) return;

    uint4 m = reinterpret_cast<const uint4*>(g_min)[i];
    uint4 c = reinterpret_cast<const uint4*>(g_cnt)[i];

    float d = __ldg(default_cost);
    float4 cost;
    cost.x = c.x ? dec_f(~m.x) : d;
    cost.y = c.y ? dec_f(~m.y) : d;
    cost.z = c.z ? dec_f(~m.z) : d;
    cost.w = c.w ? dec_f(~m.w) : d;
    reinterpret_cast<float4*>(out_cost)[i] = cost;

    if (out_mask) {
        float4 mk = make_float4((float)((int)c.x - 1), (float)((int)c.y - 1),
                                (float)((int)c.z - 1), (float)((int)c.w - 1));
        reinterpret_cast<float4*>(out_mask)[i] = mk;
    }

    // restore zero sentinels (L2-resident stores; next call starts clean)
    uint4 z = make_uint4(0u, 0u, 0u, 0u);
    reinterpret_cast<uint4*>(g_min)[i] = z;
    reinterpret_cast<uint4*>(g_cnt)[i] = z;
}

// ---------------------------------------------------------------------------
// Launcher. Inputs: points[B,N,2] f32, costs[B,N] f32, default_cost f32,
// height i32, width i32. Output: [cost | mask] as f32.
// ---------------------------------------------------------------------------
extern "C" void kernel_launch(void* const* d_in, const int* in_sizes, int n_in,
                              void* d_out, int out_size) {
    const float2* points       = (const float2*)d_in[0];
    const float*  costs        = (const float*)d_in[1];
    const float*  default_cost = (const float*)d_in[2];

    float* out_cost = (float*)d_out;
    float* out_mask = (out_size >= 2 * NCELL) ? out_cost + NCELL : nullptr;

    const int T = 256;
    dim3 sg((NPTS + T - 1) / T, BB);
    k_scatter<<<sg, T>>>(points, costs);

    k_final<<<(NCELL / 4 + T - 1) / T, T>>>(out_cost, out_mask, default_cost);
}

// round 7
// speedup vs baseline: 1.8072x; 1.3664x over previous
#include <cuda_runtime.h>
#include <cstdint>

// Problem constants: B=8, N=500000, H=W=512, HALF_CENTOR=true
#define BB    8
#define NPTS  500000
#define HH    512
#define WW    512
#define NCELL (BB * HH * WW)   // 2,097,152 cells

// Separate scratch arrays (interleaved (min,cnt) serialized in the same LTS
// atomic bank in round 2; separate 8 MB arrays hash to different partitions).
// Sentinel is 0 for both (module-load zero init); k_final restores zeros after
// reading, so every kernel_launch call / graph replay sees zeros on entry.
//   g_min[cell] = max over points of mkey = ~enc_f(cost); larger mkey ==
//                 smaller cost, and every float encodes to mkey >= 1.
//   g_cnt[cell] = number of points that hit the cell.
__device__ unsigned int g_min[NCELL];   // 8 MB
__device__ unsigned int g_cnt[NCELL];   // 8 MB

// Order-preserving float -> uint (monotone increasing).
__device__ __forceinline__ unsigned int enc_f(float f) {
    unsigned int u = __float_as_uint(f);
    return (u & 0x80000000u) ? ~u : (u | 0x80000000u);
}
__device__ __forceinline__ float dec_f(unsigned int u) {
    return __uint_as_float((u & 0x80000000u) ? (u & 0x7FFFFFFFu) : ~u);
}

// ---------------------------------------------------------------------------
// Scatter: 1 point per thread, UNCONDITIONAL fire-and-forget REDs (proven
// fastest in round 1; every load-before-atomic variant regressed badly).
// grid = (ceil(N/256), B). points [B,N,2] -> coalesced float2 loads.
// ---------------------------------------------------------------------------
__global__ void k_scatter(const float2* __restrict__ points,  // [B*N] (x,y)
                          const float*  __restrict__ costs) { // [B*N]
    int n = blockIdx.x * blockDim.x + threadIdx.x;
    int b = blockIdx.y;
    if (n >= NPTS) return;
    int gi = b * NPTS + n;
    float2 p = points[gi];

    int ix = (int)floorf(p.x + 0.5f);
    int iy = (int)floorf(p.y + 0.5f);
    if ((unsigned)ix < (unsigned)WW && (unsigned)iy < (unsigned)HH) {
        int cell = (b * HH + iy) * WW + ix;
        float c = costs[gi];
        atomicMax(&g_min[cell], ~enc_f(c));  // RED (result unused)
        atomicAdd(&g_cnt[cell], 1u);         // RED
    }
}

// ---------------------------------------------------------------------------
// Finalize: 4 cells per thread, plain stores (round-2/6 proven shape, 9.6us).
// Decodes min or default, emits mask = count-1, restores zero sentinels.
// ---------------------------------------------------------------------------
__global__ void k_final(float* __restrict__ out_cost,
                        float* __restrict__ out_mask,
                        const float* __restrict__ default_cost) {
    int i = blockIdx.x * blockDim.x + threadIdx.x;   // group of 4 cells
    if (i >= NCELL / 4) return;

    uint4 m = reinterpret_cast<const uint4*>(g_min)[i];
    uint4 c = reinterpret_cast<const uint4*>(g_cnt)[i];

    float d = __ldg(default_cost);
    float4 cost;
    cost.x = c.x ? dec_f(~m.x) : d;
    cost.y = c.y ? dec_f(~m.y) : d;
    cost.z = c.z ? dec_f(~m.z) : d;
    cost.w = c.w ? dec_f(~m.w) : d;
    reinterpret_cast<float4*>(out_cost)[i] = cost;

    if (out_mask) {
        float4 mk = make_float4((float)((int)c.x - 1), (float)((int)c.y - 1),
                                (float)((int)c.z - 1), (float)((int)c.w - 1));
        reinterpret_cast<float4*>(out_mask)[i] = mk;
    }

    // restore zero sentinels (L2-resident stores; next call starts clean)
    uint4 z = make_uint4(0u, 0u, 0u, 0u);
    reinterpret_cast<uint4*>(g_min)[i] = z;
    reinterpret_cast<uint4*>(g_cnt)[i] = z;
}

// ---------------------------------------------------------------------------
// Launcher. Inputs: points[B,N,2] f32, costs[B,N] f32, default_cost f32,
// height i32, width i32. Output: [cost | mask] as f32.
// ---------------------------------------------------------------------------
extern "C" void kernel_launch(void* const* d_in, const int* in_sizes, int n_in,
                              void* d_out, int out_size) {
    const float2* points       = (const float2*)d_in[0];
    const float*  costs        = (const float*)d_in[1];
    const float*  default_cost = (const float*)d_in[2];

    float* out_cost = (float*)d_out;
    float* out_mask = (out_size >= 2 * NCELL) ? out_cost + NCELL : nullptr;

    const int T = 256;
    dim3 sg((NPTS + T - 1) / T, BB);
    k_scatter<<<sg, T>>>(points, costs);

    k_final<<<(NCELL / 4 + T - 1) / T, T>>>(out_cost, out_mask, default_cost);
}